// round 1
// baseline (speedup 1.0000x reference)
#include <cuda_runtime.h>
#include <math.h>

#define NB   4
#define NP   19248
#define NC   81
#define NM   32
#define TOPK 100
#define KEEP 15
#define GPX  1024      // 32x32 gaussian
#define PH   138
#define PW   138
#define IH   550
#define IW   550
#define EPSF 1e-6f
#define NBINS 4096
#define TI   8
#define NT   13        // ceil(100/8)
#define NTP  91        // NT*(NT+1)/2

// ---------------- scratch (static device memory; no allocation) ----------------
__device__ float    g_conf1[NB * NP];
__device__ float    g_cval[NB][NP];
__device__ int      g_cidx[NB][NP];
__device__ int      g_ccnt[NB];
__device__ unsigned g_thr[NB];
__device__ float    g_sconf[NB][TOPK];
__device__ float    g_sloc[NB][TOPK][4];
__device__ float    g_smask[NB][TOPK][NM];
__device__ float    g_gauss[NB][TOPK][GPX];
__device__ float    g_gsum[NB][TOPK];
__device__ float    g_ioumax[NB][TOPK];     // atomicMax via positive-float int bits
__device__ float    g_kloc[NB][KEEP][4];
__device__ float    g_kmask[NB][KEEP][NM];
__device__ float    g_kconf[NB][KEEP];
__device__ float    g_final[NB][PH * PW];
__device__ double   g_acc;

// ---------------- init: zero counters / accumulators ----------------
__global__ void k_init() {
    int t = threadIdx.x;
    if (t < NB) g_ccnt[t] = 0;
    if (t == 0) g_acc = 0.0;
    for (int i = t; i < NB * TOPK; i += blockDim.x)
        (&g_ioumax[0][0])[i] = 0.f;
}

// ---------------- K1: softmax over 81 classes, keep class-1 prob ----------------
// one warp per (b,p) row
__global__ void k_softmax(const float* __restrict__ conf) {
    int warp = (blockIdx.x * blockDim.x + threadIdx.x) >> 5;
    int lane = threadIdx.x & 31;
    if (warp >= NB * NP) return;
    const float* row = conf + (size_t)warp * NC;
    float v0 = row[lane];
    float v1 = (lane + 32 < NC) ? row[lane + 32] : -INFINITY;
    float v2 = (lane + 64 < NC) ? row[lane + 64] : -INFINITY;
    float m = fmaxf(v0, fmaxf(v1, v2));
    #pragma unroll
    for (int o = 16; o; o >>= 1) m = fmaxf(m, __shfl_xor_sync(0xffffffffu, m, o));
    float s = expf(v0 - m);
    if (lane + 32 < NC) s += expf(v1 - m);
    if (lane + 64 < NC) s += expf(v2 - m);
    #pragma unroll
    for (int o = 16; o; o >>= 1) s += __shfl_xor_sync(0xffffffffu, s, o);
    float c1 = __shfl_sync(0xffffffffu, v0, 1);   // element index 1
    if (lane == 0) g_conf1[warp] = expf(c1 - m) / s;
}

// ---------------- K2a: per-batch histogram on top 13 float bits -> threshold bin ----------------
__global__ void k_hist() {
    __shared__ unsigned hist[NBINS];
    __shared__ unsigned chunk[32];
    int b = blockIdx.x, t = threadIdx.x;
    for (int i = t; i < NBINS; i += 1024) hist[i] = 0;
    __syncthreads();
    for (int i = t; i < NP; i += 1024) {
        unsigned key = __float_as_uint(g_conf1[b * NP + i]) >> 19;  // conf1 in (0,1) -> positive, monotone
        if (key > NBINS - 1) key = NBINS - 1;
        atomicAdd(&hist[key], 1u);
    }
    __syncthreads();
    int w = t >> 5, lane = t & 31;
    unsigned s = hist[w * 128 + lane] + hist[w * 128 + lane + 32] +
                 hist[w * 128 + lane + 64] + hist[w * 128 + lane + 96];
    #pragma unroll
    for (int o = 16; o; o >>= 1) s += __shfl_xor_sync(0xffffffffu, s, o);
    if (lane == 0) chunk[w] = s;
    __syncthreads();
    if (t < 32) {                       // warp 0: suffix sums over 32 chunks
        unsigned suff = chunk[t];
        #pragma unroll
        for (int o = 1; o < 32; o <<= 1) {
            unsigned x = __shfl_down_sync(0xffffffffu, suff, o);
            if (t + o < 32) suff += x;
        }
        unsigned sn = __shfl_down_sync(0xffffffffu, suff, 1);
        if (t == 31) sn = 0;
        if (suff >= TOPK && sn < TOPK) {   // exactly one lane: crossing chunk
            unsigned acc = sn;
            int thr = t * 128;
            for (int bin = t * 128 + 127; bin >= t * 128; --bin) {
                acc += hist[bin];
                if (acc >= TOPK) { thr = bin; break; }
            }
            g_thr[b] = (unsigned)thr;
        }
    }
}

// ---------------- K2b: compact all elements with key >= threshold ----------------
__global__ void k_compact() {
    int i = blockIdx.x * blockDim.x + threadIdx.x;
    if (i >= NB * NP) return;
    int b = i / NP, p = i % NP;
    float v = g_conf1[i];
    unsigned key = __float_as_uint(v) >> 19;
    if (key > NBINS - 1) key = NBINS - 1;
    if (key >= g_thr[b]) {
        int pos = atomicAdd(&g_ccnt[b], 1);
        g_cval[b][pos] = v;
        g_cidx[b][pos] = p;
    }
}

// ---------------- K2c: sort candidates (stable-equivalent composite key), take top-100, gather ----------------
__global__ void k_select(const float* __restrict__ loc, const float* __restrict__ mask) {
    __shared__ float sv[1024];
    __shared__ int   si[1024];
    __shared__ int   ss[1024];
    __shared__ int   ord[TOPK];
    int b = blockIdx.x, t = threadIdx.x;
    int cnt = g_ccnt[b];
    if (cnt <= 1024) {
        sv[t] = (t < cnt) ? g_cval[b][t] : -INFINITY;
        si[t] = (t < cnt) ? g_cidx[b][t] : 0x7fffffff;
        __syncthreads();
        // bitonic, descending by (val desc, idx asc) -- total order == stable argsort(-conf1)
        for (int k = 2; k <= 1024; k <<= 1) {
            for (int j = k >> 1; j; j >>= 1) {
                int p = t ^ j;
                if (p > t) {
                    float av = sv[t], bv = sv[p];
                    int   ai = si[t], bi = si[p];
                    bool tfirst = (av > bv) || (av == bv && ai < bi);
                    bool desc = ((t & k) == 0);
                    if (desc ? !tfirst : tfirst) {
                        sv[t] = bv; sv[p] = av; si[t] = bi; si[p] = ai;
                    }
                }
                __syncthreads();
            }
        }
        if (t < TOPK) { ord[t] = si[t]; g_sconf[b][t] = sv[t]; }
    } else {
        // fallback (practically never taken): iterative argmax over candidates
        for (int it = 0; it < TOPK; ++it) {
            float bv = -INFINITY; int bi = 0x7fffffff; int bs = -1;
            for (int s2 = t; s2 < cnt; s2 += 1024) {
                float v = g_cval[b][s2]; int ix = g_cidx[b][s2];
                if (v > bv || (v == bv && ix < bi)) { bv = v; bi = ix; bs = s2; }
            }
            sv[t] = bv; si[t] = bi; ss[t] = bs;
            __syncthreads();
            for (int o = 512; o; o >>= 1) {
                if (t < o) {
                    if (sv[t + o] > sv[t] || (sv[t + o] == sv[t] && si[t + o] < si[t])) {
                        sv[t] = sv[t + o]; si[t] = si[t + o]; ss[t] = ss[t + o];
                    }
                }
                __syncthreads();
            }
            if (t == 0) {
                ord[it] = si[0]; g_sconf[b][it] = sv[0];
                g_cval[b][ss[0]] = -INFINITY;
            }
            __syncthreads();
        }
    }
    __syncthreads();
    if (t < TOPK) {
        int idx = ord[t];
        #pragma unroll
        for (int q = 0; q < 4; q++)  g_sloc[b][t][q]  = loc[((size_t)(b * NP + idx)) * 4 + q];
        #pragma unroll
        for (int q = 0; q < NM; q++) g_smask[b][t][q] = mask[((size_t)(b * NP + idx)) * NM + q];
    }
}

// ---------------- K3: 32x32 gaussians + per-map sums ----------------
__global__ void k_gauss() {
    __shared__ float red[8];
    int b = blockIdx.x / TOPK, k = blockIdx.x % TOPK;
    int t = threadIdx.x;
    float cx = g_sloc[b][k][0], cy = g_sloc[b][k][1];
    float sx = fabsf(g_sloc[b][k][2]) * 0.5f + 0.001f;
    float sy = fabsf(g_sloc[b][k][3]) * 0.5f + 0.001f;
    float ix = 0.5f / (sx * sx), iy = 0.5f / (sy * sy);
    float lsum = 0.f;
    #pragma unroll
    for (int r = 0; r < 4; r++) {
        int px = t + 256 * r;
        int y = px >> 5, x = px & 31;
        float xs = (x + 0.5f) * (1.f / 32.f), ys = (y + 0.5f) * (1.f / 32.f);
        float dx = xs - cx, dy = ys - cy;
        float g = expf(-(dx * dx * ix + dy * dy * iy));
        g_gauss[b][k][px] = g;
        lsum += g;
    }
    #pragma unroll
    for (int o = 16; o; o >>= 1) lsum += __shfl_xor_sync(0xffffffffu, lsum, o);
    if ((t & 31) == 0) red[t >> 5] = lsum;
    __syncthreads();
    if (t == 0) {
        float s = 0;
        #pragma unroll
        for (int i = 0; i < 8; i++) s += red[i];
        g_gsum[b][k] = s;
    }
}

// ---------------- K4: tiled pairwise gaussian IoU -> iou_max[j] ----------------
// identity: inter=(S-D)/2, union=(S+D)/2, S=sumA+sumB, D=sum|a-b|  ==> only D per pair
__global__ void k_iou() {
    extern __shared__ float sh[];
    float* shA = sh;
    float* shB = sh + TI * GPX;
    int b = blockIdx.x / NTP;
    int q = blockIdx.x % NTP;
    int ti = 0;
    while (q >= NT - ti) { q -= NT - ti; ti++; }
    int tj = ti + q;
    int t = threadIdx.x;
    for (int idx = t; idx < TI * GPX; idx += 256) {
        int r = idx >> 10, px = idx & 1023;
        int gi = ti * TI + r, gj = tj * TI + r;
        shA[idx] = (gi < TOPK) ? g_gauss[b][gi][px] : 0.f;
        shB[idx] = (gj < TOPK) ? g_gauss[b][gj][px] : 0.f;
    }
    __syncthreads();
    int wp = t >> 5, l = t & 31;
    int i = ti * TI + wp;
    float a[32];
    #pragma unroll
    for (int r = 0; r < 32; r++) a[r] = shA[wp * GPX + l + 32 * r];
    float Si = (i < TOPK) ? g_gsum[b][i] : 0.f;
    for (int jr = 0; jr < TI; jr++) {
        int j = tj * TI + jr;
        if (i < j && j < TOPK) {
            float D = 0.f;
            #pragma unroll
            for (int r = 0; r < 32; r++) D += fabsf(a[r] - shB[jr * GPX + l + 32 * r]);
            #pragma unroll
            for (int o = 16; o; o >>= 1) D += __shfl_xor_sync(0xffffffffu, D, o);
            if (l == 0) {
                float S = Si + g_gsum[b][j];
                float iou = (S - D) / (S + D);        // in (0,1): int-bit atomicMax valid
                atomicMax((int*)&g_ioumax[b][j], __float_as_int(iou));
            }
        }
    }
}

// ---------------- K5: bottom-15 of iou_max (stable ascending), gather kept dets ----------------
__global__ void k_keep() {
    int b = blockIdx.x, t = threadIdx.x;  // 32 threads
    float v[4]; int id[4];
    #pragma unroll
    for (int r = 0; r < 4; r++) {
        int ix = t + 32 * r;
        id[r] = ix;
        v[r] = (ix < TOPK) ? g_ioumax[b][ix] : INFINITY;
    }
    int mykeep = -1;
    for (int it = 0; it < KEEP; ++it) {
        float bv = INFINITY; int bi = 0x7fffffff;
        #pragma unroll
        for (int r = 0; r < 4; r++)
            if (v[r] < bv || (v[r] == bv && id[r] < bi)) { bv = v[r]; bi = id[r]; }
        #pragma unroll
        for (int o = 16; o; o >>= 1) {
            float ov = __shfl_xor_sync(0xffffffffu, bv, o);
            int   oi = __shfl_xor_sync(0xffffffffu, bi, o);
            if (ov < bv || (ov == bv && oi < bi)) { bv = ov; bi = oi; }
        }
        if (t == it) mykeep = bi;
        #pragma unroll
        for (int r = 0; r < 4; r++) if (id[r] == bi) v[r] = INFINITY;
    }
    if (t < KEEP) {
        int k = mykeep;
        g_kconf[b][t] = g_sconf[b][k];
        #pragma unroll
        for (int q = 0; q < 4; q++)  g_kloc[b][t][q]  = g_sloc[b][k][q];
        #pragma unroll
        for (int m = 0; m < NM; m++) g_kmask[b][t][m] = g_smask[b][k][m];
    }
}

// ---------------- K6: final_conf per 138x138 pixel ----------------
__global__ void k_final(const float* __restrict__ proto) {
    __shared__ float skm[KEEP][NM];
    __shared__ float spr[KEEP][5];   // cx, cy, ix, iy, kconf
    int bh = blockIdx.x;
    int b = bh / PH, h = bh % PH;
    int t = threadIdx.x;             // == w, blockDim = 138
    for (int i = t; i < KEEP * NM; i += PW) skm[i / NM][i % NM] = g_kmask[b][i / NM][i % NM];
    if (t < KEEP) {
        float sx = fabsf(g_kloc[b][t][2]) * 0.5f + 0.001f;
        float sy = fabsf(g_kloc[b][t][3]) * 0.5f + 0.001f;
        spr[t][0] = g_kloc[b][t][0];
        spr[t][1] = g_kloc[b][t][1];
        spr[t][2] = 0.5f / (sx * sx);
        spr[t][3] = 0.5f / (sy * sy);
        spr[t][4] = g_kconf[b][t];
    }
    __syncthreads();
    int w = t;
    const float4* pp = (const float4*)(proto + ((size_t)(b * PH + h) * PW + w) * NM);
    float4 pv[8];
    #pragma unroll
    for (int i = 0; i < 8; i++) pv[i] = pp[i];
    float xs = (w + 0.5f) * (1.f / 138.f), ys = (h + 0.5f) * (1.f / 138.f);
    float a[KEEP]; float denom = 0.f;
    #pragma unroll
    for (int k = 0; k < KEEP; k++) {
        float dot = 0.f;
        #pragma unroll
        for (int i = 0; i < 8; i++) {
            dot = fmaf(pv[i].x, skm[k][4 * i + 0], dot);
            dot = fmaf(pv[i].y, skm[k][4 * i + 1], dot);
            dot = fmaf(pv[i].z, skm[k][4 * i + 2], dot);
            dot = fmaf(pv[i].w, skm[k][4 * i + 3], dot);
        }
        float sig = 1.f / (1.f + expf(-dot));
        float dx = xs - spr[k][0], dy = ys - spr[k][1];
        float ug = expf(-(dx * dx * spr[k][2] + dy * dy * spr[k][3]));
        float aa = sig * ug * spr[k][4];
        a[k] = aa; denom += aa;
    }
    float num = 0.f;
    #pragma unroll
    for (int k = 0; k < KEEP; k++) num = fmaf(a[k], a[k], num);
    float f = 1.f - num / (denom + EPSF);
    if (isnan(f)) f = 0.f;
    g_final[b][h * PW + w] = f;
}

// ---------------- K7: fused bilinear resize + weighted variance reduction ----------------
__global__ void k_loss(const float* __restrict__ orig) {
    __shared__ float red[8];
    int i = blockIdx.x * 256 + threadIdx.x;
    float local = 0.f;
    if (i < IH * IW) {
        int hh = i / IW, ww = i % IW;
        // jax half-pixel bilinear (normalized triangle == clamp-to-edge)
        float fy = (hh + 0.5f) * (138.f / 550.f) - 0.5f;
        float fx = (ww + 0.5f) * (138.f / 550.f) - 0.5f;
        float y0f = floorf(fy), x0f = floorf(fx);
        float wy = fy - y0f, wx = fx - x0f;
        int y0 = (int)y0f, x0 = (int)x0f;
        int y0c = min(max(y0, 0), PH - 1), y1c = min(max(y0 + 1, 0), PH - 1);
        int x0c = min(max(x0, 0), PW - 1), x1c = min(max(x0 + 1, 0), PW - 1);
        float rb[NB]; float total = 0.f;
        #pragma unroll
        for (int b = 0; b < NB; b++) {
            const float* F = g_final[b];
            float v00 = F[y0c * PW + x0c], v01 = F[y0c * PW + x1c];
            float v10 = F[y1c * PW + x0c], v11 = F[y1c * PW + x1c];
            float v = (1.f - wy) * ((1.f - wx) * v00 + wx * v01)
                    +        wy  * ((1.f - wx) * v10 + wx * v11);
            rb[b] = v; total += v;
        }
        float acc = 0.f;
        #pragma unroll
        for (int c = 0; c < 3; c++) {
            float ob[NB]; float wm = 0.f;
            #pragma unroll
            for (int b = 0; b < NB; b++) {
                ob[b] = orig[(((size_t)(b * 3 + c)) * IH + hh) * IW + ww];
                wm = fmaf(ob[b], rb[b], wm);
            }
            #pragma unroll
            for (int b = 0; b < NB; b++) {
                float d = ob[b] - wm;
                acc = fmaf(d * d, rb[b], acc);
            }
        }
        local = acc / (total + EPSF);
    }
    int t = threadIdx.x;
    float s = local;
    #pragma unroll
    for (int o = 16; o; o >>= 1) s += __shfl_xor_sync(0xffffffffu, s, o);
    if ((t & 31) == 0) red[t >> 5] = s;
    __syncthreads();
    if (t == 0) {
        float bs = 0.f;
        #pragma unroll
        for (int q = 0; q < 8; q++) bs += red[q];
        atomicAdd(&g_acc, (double)bs);
    }
}

__global__ void k_out(float* out) { out[0] = (float)(g_acc * 0.01); }

// ---------------- launch ----------------
extern "C" void kernel_launch(void* const* d_in, const int* in_sizes, int n_in,
                              void* d_out, int out_size) {
    const float* orig  = (const float*)d_in[0];
    const float* loc   = (const float*)d_in[1];
    const float* conf  = (const float*)d_in[2];
    const float* mask  = (const float*)d_in[3];
    const float* proto = (const float*)d_in[4];
    float* out = (float*)d_out;

    k_init<<<1, 256>>>();
    k_softmax<<<(NB * NP) / 8, 256>>>(conf);           // one warp/row, exact
    k_hist<<<NB, 1024>>>();
    k_compact<<<(NB * NP + 255) / 256, 256>>>();
    k_select<<<NB, 1024>>>(loc, mask);
    k_gauss<<<NB * TOPK, 256>>>();
    cudaFuncSetAttribute(k_iou, cudaFuncAttributeMaxDynamicSharedMemorySize, 2 * TI * GPX * 4);
    k_iou<<<NB * NTP, 256, 2 * TI * GPX * 4>>>();
    k_keep<<<NB, 32>>>();
    k_final<<<NB * PH, PW>>>(proto);
    k_loss<<<(IH * IW + 255) / 256, 256>>>(orig);
    k_out<<<1, 1>>>(out);
}

// round 2
// speedup vs baseline: 1.2833x; 1.2833x over previous
#include <cuda_runtime.h>
#include <math.h>

#define NB   4
#define NP   19248
#define NC   81
#define NM   32
#define TOPK 100
#define CAND 108       // candidate margin over TOPK
#define KEEP 15
#define GPX  1024      // 32x32 gaussian
#define PH   138
#define PW   138
#define IH   550
#define IW   550
#define EPSF 1e-6f
#define NBINS 4096
#define TI   8
#define NT   13        // ceil(100/8)
#define NTP  91        // NT*(NT+1)/2
#define FCH  75        // chunks of 256 px covering 138*138 per batch

// ---------------- scratch (static device memory) ----------------
__device__ float    g_key[NB * NP];
__device__ float    g_sconf[NB][TOPK];
__device__ float    g_sloc[NB][TOPK][4];
__device__ float    g_smask[NB][TOPK][NM];
__device__ float    g_ioumax[NB][TOPK];     // atomicMax via positive-float int bits
__device__ float    g_final[NB][PH * PW];
__device__ double   g_acc;
__device__ unsigned g_done;

// ---------------- fast math on FMA pipe ----------------
// exp(x), rel err ~1.2e-7, ~11 ops, no MUFU
__device__ __forceinline__ float fexp(float x) {
    x = fminf(fmaxf(x, -87.0f), 88.0f);
    float t = x * 1.4426950408889634f;
    float fi = rintf(t);
    float f = t - fi;
    float p =            1.5403530e-4f;
    p = fmaf(p, f, 1.3333558e-3f);
    p = fmaf(p, f, 9.6181291e-3f);
    p = fmaf(p, f, 5.5504109e-2f);
    p = fmaf(p, f, 2.4022651e-1f);
    p = fmaf(p, f, 6.9314718e-1f);
    p = fmaf(p, f, 1.0f);
    int ei = (int)fi;
    return p * __int_as_float((ei + 127) << 23);
}
// 1/y, rel err ~1e-10 for normal positive y, ~8 ops, no MUFU
__device__ __forceinline__ float frcp(float y) {
    float r = __int_as_float(0x7EF311C3 - __float_as_int(y));
    r = r * (2.0f - y * r);
    r = r * (2.0f - y * r);
    r = r * (2.0f - y * r);
    return r;
}

// ---------------- K1: ordering key per anchor (monotone in conf1) ----------------
// key = (c1 - m)*log2e - log2(sum exp(ci - m)); one warp per row
__global__ void k_score(const float* __restrict__ conf) {
    int warp = (blockIdx.x * blockDim.x + threadIdx.x) >> 5;
    int lane = threadIdx.x & 31;
    if (warp >= NB * NP) return;
    const float* row = conf + (size_t)warp * NC;
    float v0 = row[lane];
    float v1 = (lane + 32 < NC) ? row[lane + 32] : -INFINITY;
    float v2 = (lane + 64 < NC) ? row[lane + 64] : -INFINITY;
    float m = fmaxf(v0, fmaxf(v1, v2));
    #pragma unroll
    for (int o = 16; o; o >>= 1) m = fmaxf(m, __shfl_xor_sync(0xffffffffu, m, o));
    float s = fexp(v0 - m);
    if (lane + 32 < NC) s += fexp(v1 - m);
    if (lane + 64 < NC) s += fexp(v2 - m);
    #pragma unroll
    for (int o = 16; o; o >>= 1) s += __shfl_xor_sync(0xffffffffu, s, o);
    float c1 = __shfl_sync(0xffffffffu, v0, 1);
    if (lane == 0) g_key[warp] = (c1 - m) * 1.4426950408889634f - __log2f(s);
}

__device__ __forceinline__ unsigned key_bucket(float k) {
    unsigned u = __float_as_uint(k);
    u = (u & 0x80000000u) ? ~u : (u | 0x80000000u);
    unsigned b = u >> 19;
    return b > (NBINS - 1) ? (NBINS - 1) : b;
}

// ---------------- K2: one block per batch: hist -> threshold -> compact ->
//                   exact conf1 recompute -> stable sort -> gather top-100 ----------------
__global__ void k_select(const float* __restrict__ conf,
                         const float* __restrict__ loc,
                         const float* __restrict__ mask) {
    __shared__ unsigned s_hist[NBINS];
    __shared__ unsigned s_chunk[32];
    __shared__ int s_cnt, s_thr;
    __shared__ float s_val[1024];
    __shared__ int   s_idx[1024];
    int b = blockIdx.x, t = threadIdx.x;
    int lane = t & 31, wp = t >> 5;

    for (int i = t; i < NBINS; i += 1024) s_hist[i] = 0;
    if (t == 0) s_cnt = 0;
    __syncthreads();
    // pass 1: histogram
    for (int i = t; i < NP; i += 1024)
        atomicAdd(&s_hist[key_bucket(g_key[b * NP + i])], 1u);
    __syncthreads();
    // threshold: highest bin such that suffix count >= CAND
    unsigned cs = s_hist[wp * 128 + lane] + s_hist[wp * 128 + lane + 32] +
                  s_hist[wp * 128 + lane + 64] + s_hist[wp * 128 + lane + 96];
    #pragma unroll
    for (int o = 16; o; o >>= 1) cs += __shfl_xor_sync(0xffffffffu, cs, o);
    if (lane == 0) s_chunk[wp] = cs;
    __syncthreads();
    if (t < 32) {
        unsigned suff = s_chunk[t];
        #pragma unroll
        for (int o = 1; o < 32; o <<= 1) {
            unsigned x = __shfl_down_sync(0xffffffffu, suff, o);
            if (t + o < 32) suff += x;
        }
        unsigned sn = __shfl_down_sync(0xffffffffu, suff, 1);
        if (t == 31) sn = 0;
        if (suff >= CAND && sn < CAND) {
            unsigned acc = sn;
            int thr = t * 128;
            for (int bin = t * 128 + 127; bin >= t * 128; --bin) {
                acc += s_hist[bin];
                if (acc >= CAND) { thr = bin; break; }
            }
            s_thr = thr;
        }
    }
    __syncthreads();
    // pass 2: compact candidate indices
    int thr = s_thr;
    for (int i = t; i < NP; i += 1024) {
        if ((int)key_bucket(g_key[b * NP + i]) >= thr) {
            int pos = atomicAdd(&s_cnt, 1);
            if (pos < 1024) s_idx[pos] = i;
        }
    }
    __syncthreads();
    int cnt = s_cnt; if (cnt > 1024) cnt = 1024;
    // exact conf1 for candidates (accurate expf; tiny count)
    for (int c = wp; c < cnt; c += 32) {
        const float* row = conf + (size_t)(b * NP + s_idx[c]) * NC;
        float v0 = row[lane];
        float v1 = (lane + 32 < NC) ? row[lane + 32] : -INFINITY;
        float v2 = (lane + 64 < NC) ? row[lane + 64] : -INFINITY;
        float m = fmaxf(v0, fmaxf(v1, v2));
        #pragma unroll
        for (int o = 16; o; o >>= 1) m = fmaxf(m, __shfl_xor_sync(0xffffffffu, m, o));
        float s = expf(v0 - m);
        if (lane + 32 < NC) s += expf(v1 - m);
        if (lane + 64 < NC) s += expf(v2 - m);
        #pragma unroll
        for (int o = 16; o; o >>= 1) s += __shfl_xor_sync(0xffffffffu, s, o);
        float c1 = __shfl_sync(0xffffffffu, v0, 1);
        if (lane == 0) s_val[c] = expf(c1 - m) / s;
    }
    __syncthreads();
    int S = 1; while (S < cnt) S <<= 1;
    if (t >= cnt && t < S) { s_val[t] = -INFINITY; s_idx[t] = 0x7fffffff; }
    __syncthreads();
    // bitonic: (val desc, idx asc) == stable argsort(-conf1)
    for (int k2 = 2; k2 <= S; k2 <<= 1) {
        for (int j = k2 >> 1; j; j >>= 1) {
            if (t < S) {
                int p = t ^ j;
                if (p > t) {
                    float av = s_val[t], bv = s_val[p];
                    int   ai = s_idx[t], bi = s_idx[p];
                    bool tfirst = (av > bv) || (av == bv && ai < bi);
                    bool desc = ((t & k2) == 0);
                    if (desc ? !tfirst : tfirst) {
                        s_val[t] = bv; s_val[p] = av; s_idx[t] = bi; s_idx[p] = ai;
                    }
                }
            }
            __syncthreads();
        }
    }
    if (t < TOPK) {
        int idx = s_idx[t];
        g_sconf[b][t] = s_val[t];
        *(float4*)&g_sloc[b][t][0] = *(const float4*)(loc + (size_t)(b * NP + idx) * 4);
        const float4* mp = (const float4*)(mask + (size_t)(b * NP + idx) * NM);
        float4* dst = (float4*)&g_smask[b][t][0];
        #pragma unroll
        for (int q = 0; q < 8; q++) dst[q] = mp[q];
        g_ioumax[b][t] = 0.f;
    }
    if (b == 0 && t == 0) { g_acc = 0.0; g_done = 0u; }
}

// ---------------- K3: fused gaussian generation + tiled pairwise IoU ----------------
// inter=(S-D)/2, union=(S+D)/2 with D=sum|a-b|; maps regenerated in-block (no global round trip)
__global__ void k_iou() {
    __shared__ float shB[TI][GPX];
    __shared__ float shS[TI];
    int b = blockIdx.x / NTP;
    int q = blockIdx.x % NTP;
    int ti = 0;
    while (q >= NT - ti) { q -= NT - ti; ti++; }
    int tj = ti + q;
    int t = threadIdx.x, wp = t >> 5, l = t & 31;
    float xs = (l + 0.5f) * (1.f / 32.f);

    // A rows in registers: warp wp owns det i
    int i = ti * TI + wp;
    int ic = min(i, TOPK - 1);
    float cx = g_sloc[b][ic][0], cy = g_sloc[b][ic][1];
    float sx = fabsf(g_sloc[b][ic][2]) * 0.5f + 0.001f;
    float sy = fabsf(g_sloc[b][ic][3]) * 0.5f + 0.001f;
    float ix = 0.5f * frcp(sx * sx), iy = 0.5f * frcp(sy * sy);
    float dxq = (xs - cx); dxq = dxq * dxq * ix;
    float a[32]; float Si = 0.f;
    #pragma unroll
    for (int r = 0; r < 32; r++) {
        float dy = (r + 0.5f) * (1.f / 32.f) - cy;
        float g = fexp(-fmaf(dy * dy, iy, dxq));
        a[r] = g; Si += g;
    }
    #pragma unroll
    for (int o = 16; o; o >>= 1) Si += __shfl_xor_sync(0xffffffffu, Si, o);

    // B rows into smem: warp wp owns det j
    int j = tj * TI + wp;
    int jc = min(j, TOPK - 1);
    float bx = g_sloc[b][jc][0], by = g_sloc[b][jc][1];
    float bsx = fabsf(g_sloc[b][jc][2]) * 0.5f + 0.001f;
    float bsy = fabsf(g_sloc[b][jc][3]) * 0.5f + 0.001f;
    float bix = 0.5f * frcp(bsx * bsx), biy = 0.5f * frcp(bsy * bsy);
    float bdxq = (xs - bx); bdxq = bdxq * bdxq * bix;
    float Sj = 0.f;
    #pragma unroll
    for (int r = 0; r < 32; r++) {
        float dy = (r + 0.5f) * (1.f / 32.f) - by;
        float g = fexp(-fmaf(dy * dy, biy, bdxq));
        shB[wp][r * 32 + l] = g; Sj += g;
    }
    #pragma unroll
    for (int o = 16; o; o >>= 1) Sj += __shfl_xor_sync(0xffffffffu, Sj, o);
    if (l == 0) shS[wp] = Sj;
    __syncthreads();

    for (int jr = 0; jr < TI; jr++) {
        int jj = tj * TI + jr;
        if (i < jj && jj < TOPK) {
            float D = 0.f;
            #pragma unroll
            for (int r = 0; r < 32; r++) D += fabsf(a[r] - shB[jr][r * 32 + l]);
            #pragma unroll
            for (int o = 16; o; o >>= 1) D += __shfl_xor_sync(0xffffffffu, D, o);
            if (l == 0) {
                float S = Si + shS[jr];
                float iou = (S - D) * frcp(S + D);     // in (0,1): int-bit atomicMax valid
                atomicMax((int*)&g_ioumax[b][jj], __float_as_int(iou));
            }
        }
    }
}

// ---------------- K4: keep-15 (recomputed per block) + final_conf per proto pixel ----------------
__global__ void k_final(const float* __restrict__ proto) {
    __shared__ float skm[KEEP][NM];
    __shared__ float spr[KEEP][5];   // cx, cy, ix, iy, kconf
    __shared__ int   skidx[KEEP];
    int bx = blockIdx.x;
    int b = bx / FCH, chunk = bx % FCH;
    int t = threadIdx.x;
    if (t < 32) {
        // bottom-15 of iou_max, stable ascending (== jnp.argsort)
        float v[4]; int id[4];
        #pragma unroll
        for (int r = 0; r < 4; r++) {
            int ixp = t + 32 * r; id[r] = ixp;
            v[r] = (ixp < TOPK) ? g_ioumax[b][ixp] : INFINITY;
        }
        int mykeep = -1;
        for (int it = 0; it < KEEP; ++it) {
            float bv = INFINITY; int bi = 0x7fffffff;
            #pragma unroll
            for (int r = 0; r < 4; r++)
                if (v[r] < bv || (v[r] == bv && id[r] < bi)) { bv = v[r]; bi = id[r]; }
            #pragma unroll
            for (int o = 16; o; o >>= 1) {
                float ov = __shfl_xor_sync(0xffffffffu, bv, o);
                int   oi = __shfl_xor_sync(0xffffffffu, bi, o);
                if (ov < bv || (ov == bv && oi < bi)) { bv = ov; bi = oi; }
            }
            if (t == it) mykeep = bi;
            #pragma unroll
            for (int r = 0; r < 4; r++) if (id[r] == bi) v[r] = INFINITY;
        }
        if (t < KEEP) {
            int k = mykeep;
            skidx[t] = k;
            float sx = fabsf(g_sloc[b][k][2]) * 0.5f + 0.001f;
            float sy = fabsf(g_sloc[b][k][3]) * 0.5f + 0.001f;
            spr[t][0] = g_sloc[b][k][0];
            spr[t][1] = g_sloc[b][k][1];
            spr[t][2] = 0.5f * frcp(sx * sx);
            spr[t][3] = 0.5f * frcp(sy * sy);
            spr[t][4] = g_sconf[b][k];
        }
    }
    __syncthreads();
    for (int i2 = t; i2 < KEEP * NM; i2 += 256)
        skm[i2 / NM][i2 % NM] = g_smask[b][skidx[i2 / NM]][i2 % NM];
    __syncthreads();

    int px = chunk * 256 + t;
    if (px >= PH * PW) return;
    int h = px / PW, w = px % PW;
    const float4* pp = (const float4*)(proto + ((size_t)(b * PH + h) * PW + w) * NM);
    float4 pv[8];
    #pragma unroll
    for (int i2 = 0; i2 < 8; i2++) pv[i2] = pp[i2];
    float xs = (w + 0.5f) * (1.f / 138.f), ys = (h + 0.5f) * (1.f / 138.f);
    float a[KEEP]; float denom = 0.f;
    #pragma unroll
    for (int k = 0; k < KEEP; k++) {
        float dot = 0.f;
        #pragma unroll
        for (int i2 = 0; i2 < 8; i2++) {
            dot = fmaf(pv[i2].x, skm[k][4 * i2 + 0], dot);
            dot = fmaf(pv[i2].y, skm[k][4 * i2 + 1], dot);
            dot = fmaf(pv[i2].z, skm[k][4 * i2 + 2], dot);
            dot = fmaf(pv[i2].w, skm[k][4 * i2 + 3], dot);
        }
        float sig = frcp(1.f + fexp(-dot));
        float dx = xs - spr[k][0], dy = ys - spr[k][1];
        float ug = fexp(-(dx * dx * spr[k][2] + dy * dy * spr[k][3]));
        float aa = sig * ug * spr[k][4];
        a[k] = aa; denom += aa;
    }
    float num = 0.f;
    #pragma unroll
    for (int k = 0; k < KEEP; k++) num = fmaf(a[k], a[k], num);
    float f = 1.f - num * frcp(denom + EPSF);
    if (isnan(f)) f = 0.f;
    g_final[b][px] = f;
}

// ---------------- K5: fused bilinear resize + weighted variance + final output ----------------
__global__ void k_loss(const float* __restrict__ orig, float* __restrict__ out) {
    __shared__ float red[8];
    int i = blockIdx.x * 256 + threadIdx.x;
    float local = 0.f;
    if (i < IH * IW) {
        int hh = i / IW, ww = i % IW;
        float fy = (hh + 0.5f) * (138.f / 550.f) - 0.5f;
        float fx = (ww + 0.5f) * (138.f / 550.f) - 0.5f;
        float y0f = floorf(fy), x0f = floorf(fx);
        float wy = fy - y0f, wx = fx - x0f;
        int y0 = (int)y0f, x0 = (int)x0f;
        int y0c = min(max(y0, 0), PH - 1), y1c = min(max(y0 + 1, 0), PH - 1);
        int x0c = min(max(x0, 0), PW - 1), x1c = min(max(x0 + 1, 0), PW - 1);
        float rb[NB]; float total = 0.f;
        #pragma unroll
        for (int b = 0; b < NB; b++) {
            const float* F = g_final[b];
            float v00 = F[y0c * PW + x0c], v01 = F[y0c * PW + x1c];
            float v10 = F[y1c * PW + x0c], v11 = F[y1c * PW + x1c];
            float v = (1.f - wy) * ((1.f - wx) * v00 + wx * v01)
                    +        wy  * ((1.f - wx) * v10 + wx * v11);
            rb[b] = v; total += v;
        }
        float acc = 0.f;
        #pragma unroll
        for (int c = 0; c < 3; c++) {
            float ob[NB]; float wm = 0.f;
            #pragma unroll
            for (int b = 0; b < NB; b++) {
                ob[b] = orig[(((size_t)(b * 3 + c)) * IH + hh) * IW + ww];
                wm = fmaf(ob[b], rb[b], wm);
            }
            #pragma unroll
            for (int b = 0; b < NB; b++) {
                float d = ob[b] - wm;
                acc = fmaf(d * d, rb[b], acc);
            }
        }
        local = acc * frcp(total + EPSF);
    }
    int t = threadIdx.x;
    float s = local;
    #pragma unroll
    for (int o = 16; o; o >>= 1) s += __shfl_xor_sync(0xffffffffu, s, o);
    if ((t & 31) == 0) red[t >> 5] = s;
    __syncthreads();
    if (t == 0) {
        float bs = 0.f;
        #pragma unroll
        for (int q2 = 0; q2 < 8; q2++) bs += red[q2];
        atomicAdd(&g_acc, (double)bs);
        __threadfence();
        unsigned v = atomicAdd(&g_done, 1u);
        if (v == gridDim.x - 1)
            out[0] = (float)(*((volatile double*)&g_acc) * 0.01);
    }
}

// ---------------- launch: 5 graph nodes ----------------
extern "C" void kernel_launch(void* const* d_in, const int* in_sizes, int n_in,
                              void* d_out, int out_size) {
    const float* orig  = (const float*)d_in[0];
    const float* loc   = (const float*)d_in[1];
    const float* conf  = (const float*)d_in[2];
    const float* mask  = (const float*)d_in[3];
    const float* proto = (const float*)d_in[4];
    float* out = (float*)d_out;

    k_score<<<(NB * NP + 7) / 8, 256>>>(conf);
    k_select<<<NB, 1024>>>(conf, loc, mask);
    k_iou<<<NB * NTP, 256>>>();
    k_final<<<NB * FCH, 256>>>(proto);
    k_loss<<<(IH * IW + 255) / 256, 256>>>(orig, out);
}